// round 6
// baseline (speedup 1.0000x reference)
#include <cuda_runtime.h>

#define NN 65536
#define EE 524288
#define GG 64

// ---------------- scratch ----------------------------------------------------
__device__ __align__(16) int   g_degi[NN];       // in-degree
__device__ __align__(16) float g_dinv[NN];
__device__ __align__(16) int   g_base[NN];
__device__ __align__(16) int   g_cur[NN];
__device__ __align__(16) int   g_meta[EE];       // src only (4B/edge)
__device__ __align__(16) float g_xws2[NN * 64];  // dinv-prescaled xw2
__device__ __align__(16) float g_xws3[NN * 32];  // dinv-prescaled xw3
__device__ __align__(16) float g_h3r[NN * 32];   // relu(h3in + b3)
__device__ __align__(16) float g_psum[GG * 32];
__device__ __align__(16) float g_pcnt[GG];
__device__ int g_ctr;
// piecewise-linear table for xw2(s) = A[seg]*s + B[seg]
__device__ __align__(16) float g_knots[128];
__device__ __align__(16) float g_A[129 * 64];
__device__ __align__(16) float g_B[129 * 64];

// ---------------- init --------------------------------------------------------
__global__ void k_init() {
    int i = blockIdx.x * blockDim.x + threadIdx.x;   // NN threads
    g_degi[i] = 0;
    if (i < GG * 32) g_psum[i] = 0.f;
    if (i < GG)      g_pcnt[i] = 0.f;
    if (i == 0)      g_ctr = 0;
}

// ---------------- degree (4 edges / thread, no-return REDs) --------------------
__global__ void k_deg(const int* __restrict__ ei) {
    int t = blockIdx.x * blockDim.x + threadIdx.x;   // EE/4 threads
    int4 d4 = ((const int4*)(ei + EE))[t];
    atomicAdd(&g_degi[d4.x], 1);
    atomicAdd(&g_degi[d4.y], 1);
    atomicAdd(&g_degi[d4.z], 1);
    atomicAdd(&g_degi[d4.w], 1);
}

// ---------------- dinv + CSR bases, with PWL-table build riding along ----------
__global__ __launch_bounds__(256) void k_dinvpw2(const float* __restrict__ W1,
                                                 const float* __restrict__ b1,
                                                 const float* __restrict__ W2) {
    if (blockIdx.x < NN / 256) {
        int i = blockIdx.x * 256 + threadIdx.x;
        int cnt = g_degi[i];
        g_dinv[i] = rsqrtf((float)(cnt + 1));
        int base = atomicAdd(&g_ctr, cnt);
        g_base[i] = base;
        g_cur[i]  = base;
        return;
    }
    // ---- last block: build PWL table (xw2(s) is PWL in s, knots -b1/W1) ----
    __shared__ float sw1[128], sb1[128], thr[128], sk[128];
    __shared__ int sidx[128];
    int t = threadIdx.x;
    if (t < 128) {
        float w = W1[t], b = b1[t];
        sw1[t] = w; sb1[t] = b;
        thr[t] = (w != 0.f) ? (-b / w) : 3.4e38f;
    }
    __syncthreads();
    if (t < 128) {
        float th = thr[t];
        int pos = 0;
        for (int j = 0; j < 128; j++) {
            float o = thr[j];
            pos += (o < th) || (o == th && j < t);
        }
        sk[pos] = th; sidx[pos] = t;
    }
    __syncthreads();
    if (t < 128) g_knots[t] = sk[t];
    if (t < 64) {
        float a = 0.f, bb = 0.f;
        for (int f = 0; f < 128; f++) {
            float w1 = sw1[f], b1v = sb1[f];
            if ((w1 < 0.f) || (w1 == 0.f && b1v > 0.f)) {
                float w2 = W2[f * 64 + t];
                a = fmaf(w1, w2, a); bb = fmaf(b1v, w2, bb);
            }
        }
        g_A[t] = a; g_B[t] = bb;
        for (int j = 0; j < 128; j++) {
            int f = sidx[j]; float w1 = sw1[f];
            if (w1 > 0.f) {
                float w2 = W2[f * 64 + t];
                a = fmaf(w1, w2, a); bb = fmaf(sb1[f], w2, bb);
            } else if (w1 < 0.f) {
                float w2 = W2[f * 64 + t];
                a = fmaf(-w1, w2, a); bb = fmaf(-sb1[f], w2, bb);
            }
            g_A[(j + 1) * 64 + t] = a; g_B[(j + 1) * 64 + t] = bb;
        }
    }
}

// ---------------- CSR fill: per-edge src grouped by dst ------------------------
__global__ void k_fill(const int* __restrict__ ei) {
    int t = blockIdx.x * blockDim.x + threadIdx.x;   // EE/4 threads
    int4 s4 = ((const int4*)ei)[t];
    int4 d4 = ((const int4*)(ei + EE))[t];
    g_meta[atomicAdd(&g_cur[d4.x], 1)] = s4.x;
    g_meta[atomicAdd(&g_cur[d4.y], 1)] = s4.y;
    g_meta[atomicAdd(&g_cur[d4.z], 1)] = s4.z;
    g_meta[atomicAdd(&g_cur[d4.w], 1)] = s4.w;
}

// ------- fused: layer-1 scalar gather + PWL eval -> xws2 = dinv*xw2 ------------
__global__ __launch_bounds__(256) void k_s1xw2(const float* __restrict__ x) {
    __shared__ float sk[128];
    int t = threadIdx.x;
    if (t < 128) sk[t] = g_knots[t];
    __syncthreads();
    int node = (blockIdx.x * 256 + t) >> 5;           // NN warps
    int lane = t & 31;
    int base = g_base[node], cnt = g_degi[node];
    float di = g_dinv[node];
    float v = 0.f;
    if (lane < cnt) {
        int s = g_meta[base + lane];
        v = x[s] * g_dinv[s];
    }
    for (int j = 32 + lane; j < cnt; j += 32) {
        int s = g_meta[base + j];
        v = fmaf(x[s], g_dinv[s], v);
    }
#pragma unroll
    for (int o = 16; o; o >>= 1) v += __shfl_xor_sync(0xffffffff, v, o);
    float s1 = di * fmaf(x[node], di, v);
    int seg = 0;
#pragma unroll
    for (int step = 128; step; step >>= 1) {
        int m = seg + step;
        if (m <= 128 && sk[m - 1] < s1) seg = m;
    }
    if (lane < 16) {
        float4 A = *(const float4*)&g_A[seg * 64 + lane * 4];
        float4 B = *(const float4*)&g_B[seg * 64 + lane * 4];
        float4 r;
        r.x = fmaf(A.x, s1, B.x) * di; r.y = fmaf(A.y, s1, B.y) * di;
        r.z = fmaf(A.z, s1, B.z) * di; r.w = fmaf(A.w, s1, B.w) * di;
        *(float4*)&g_xws2[node * 64 + lane * 4] = r;
    }
}

// ------- fused: layer-2 gather + relu + @W3 -> xws3 = dinv*xw3 ------------------
__global__ __launch_bounds__(256) void k_gat2mm3(const float* __restrict__ b2,
                                                 const float* __restrict__ W3) {
    __shared__ __align__(16) float W3s[64 * 32];      // 8 KB
    int t = threadIdx.x;
    ((float4*)W3s)[t]       = ((const float4*)W3)[t];
    ((float4*)W3s)[t + 256] = ((const float4*)W3)[t + 256];
    __syncthreads();
    int node = (blockIdx.x * 256 + t) >> 5;
    int lane = t & 31;
    int base = g_base[node], cnt = g_degi[node];
    float di = g_dinv[node];
    float2 acc = *(const float2*)&g_xws2[node * 64 + lane * 2];   // self
    int nfull = min(cnt, 32);
    int me = 0;
    if (lane < nfull) me = g_meta[base + lane];
    for (int j = 0; j < nfull; j++) {
        int s = __shfl_sync(0xffffffff, me, j);
        float2 vv = *(const float2*)&g_xws2[s * 64 + lane * 2];
        acc.x += vv.x; acc.y += vv.y;
    }
    for (int j = 32; j < cnt; j++) {
        int s = g_meta[base + j];
        float2 vv = *(const float2*)&g_xws2[s * 64 + lane * 2];
        acc.x += vv.x; acc.y += vv.y;
    }
    float2 h;
    h.x = fmaxf(fmaf(di, acc.x, b2[2 * lane]), 0.f);
    h.y = fmaxf(fmaf(di, acc.y, b2[2 * lane + 1]), 0.f);
    float o = 0.f;
#pragma unroll
    for (int k2 = 0; k2 < 32; k2++) {
        float he = __shfl_sync(0xffffffff, h.x, k2);
        float ho = __shfl_sync(0xffffffff, h.y, k2);
        o = fmaf(he, W3s[(2 * k2) * 32 + lane], o);
        o = fmaf(ho, W3s[(2 * k2 + 1) * 32 + lane], o);
    }
    g_xws3[node * 32 + lane] = o * di;
}

// ------- layer-3 gather + bias + relu -------------------------------------------
__global__ __launch_bounds__(256) void k_gat3(const float* __restrict__ b3) {
    int t = threadIdx.x;
    int node = (blockIdx.x * 256 + t) >> 5;
    int lane = t & 31;
    int base = g_base[node], cnt = g_degi[node];
    float di = g_dinv[node];
    float acc = g_xws3[node * 32 + lane];             // self
    int nfull = min(cnt, 32);
    int me = 0;
    if (lane < nfull) me = g_meta[base + lane];
    for (int j = 0; j < nfull; j++) {
        int s = __shfl_sync(0xffffffff, me, j);
        acc += g_xws3[s * 32 + lane];
    }
    for (int j = 32; j < cnt; j++) {
        int s = g_meta[base + j];
        acc += g_xws3[s * 32 + lane];
    }
    g_h3r[node * 32 + lane] = fmaxf(fmaf(di, acc, b3[lane]), 0.f);
}

// ---------------- pool: run-length segmented sum ---------------------------------
__global__ __launch_bounds__(256) void k_pool(const int* __restrict__ batch) {
    int t = threadIdx.x;
    int f = t & 31, s = t >> 5;
    const int NB = NN / 64;
    int base = blockIdx.x * NB;

    float acc = 0.f, cnt = 0.f;
    int curb = batch[base + s];
#pragma unroll 4
    for (int i = 0; i < NB / 8; i++) {
        int node = base + s + i * 8;
        int b = batch[node];
        if (b != curb) {
            atomicAdd(&g_psum[curb * 32 + f], acc);
            if (f == 0) atomicAdd(&g_pcnt[curb], cnt);
            acc = 0.f; cnt = 0.f; curb = b;
        }
        acc += g_h3r[node * 32 + f];
        cnt += 1.f;
    }
    atomicAdd(&g_psum[curb * 32 + f], acc);
    if (f == 0) atomicAdd(&g_pcnt[curb], cnt);
}

// ---------------- final FC ---------------------------------------------------------
__global__ void k_fc(const float* __restrict__ Wfc, const float* __restrict__ bfc,
                     float* __restrict__ out) {
    int t = threadIdx.x;
    if (t < GG * 10) {
        int g = t / 10, o = t % 10;
        float inv = 1.0f / fmaxf(g_pcnt[g], 1.0f);
        float acc = bfc[o];
#pragma unroll
        for (int f = 0; f < 32; f++)
            acc = fmaf(g_psum[g * 32 + f] * inv, Wfc[f * 10 + o], acc);
        out[g * 10 + o] = acc;
    }
}

// ---------------- launch -------------------------------------------------------------
extern "C" void kernel_launch(void* const* d_in, const int* in_sizes, int n_in,
                              void* d_out, int out_size) {
    const float* x     = (const float*)d_in[0];
    const int*   ei    = (const int*)d_in[1];
    const int*   batch = (const int*)d_in[2];
    const float* W1    = (const float*)d_in[3];
    const float* b1    = (const float*)d_in[4];
    const float* W2    = (const float*)d_in[5];
    const float* b2    = (const float*)d_in[6];
    const float* W3    = (const float*)d_in[7];
    const float* b3    = (const float*)d_in[8];
    const float* Wfc   = (const float*)d_in[9];
    const float* bfc   = (const float*)d_in[10];
    float* out = (float*)d_out;

    k_init   <<<NN / 256, 256>>>();
    k_deg    <<<EE / 4 / 256, 256>>>(ei);
    k_dinvpw2<<<NN / 256 + 1, 256>>>(W1, b1, W2);
    k_fill   <<<EE / 4 / 256, 256>>>(ei);
    k_s1xw2  <<<NN * 32 / 256, 256>>>(x);
    k_gat2mm3<<<NN * 32 / 256, 256>>>(b2, W3);
    k_gat3   <<<NN * 32 / 256, 256>>>(b3);
    k_pool   <<<64, 256>>>(batch);
    k_fc     <<<1, 640>>>(Wfc, bfc, out);
}